// round 16
// baseline (speedup 1.0000x reference)
#include <cuda_runtime.h>
#include <cuda_fp16.h>
#include <math_constants.h>
#include <cstdint>

// Problem constants (fixed by dataset: B=2, H=96, W=96, P=32)
#define NTHREADS 256
#define RS2 136   // h1/h2 row stride in half2 units: 544 B == 32 (mod 128) ->
                  // conflict-free LDS.64 fragment phases
#define CS  264   // C row stride (floats): 1056 B == 32 (mod 128)

// Scratch (allocation-free rule: __device__ globals).
// uint4 fragment-major fp16 weights for mma.m16n8k16.f16:
//   slot (k16, np, lane): j=lane&3, nsub=lane>>2,
//     n0 = np*16 + nsub, n1 = n0 + 8   (covers n8 groups 2np, 2np+1)
//   .x = half2(W[n0][kb+2j],   W[n0][kb+2j+1])    (b0 of n8g=2np)
//   .y = half2(W[n0][kb+8+2j], W[n0][kb+8+2j+1])  (b1 of n8g=2np)
//   .z/.w = same with n1                           (n8g=2np+1)
// W3H4 padded by 2 k16 groups (zero) so the distance-2 prefetch may over-read.
__device__ float g_zfeat[256];
__device__ __align__(16) uint4 g_W2H4[2 * 512];
__device__ __align__(16) uint4 g_W3H4[(16 + 2) * 512];

// ---------------------------------------------------------------------------
// Prep (grid 37 x 256): blocks 0-31 W3H4, 32-35 W2H4, 36 zfeat (full fp32).
// ---------------------------------------------------------------------------
__global__ void prep_kernel(const float* __restrict__ W2,
                            const float* __restrict__ W3,
                            const float* __restrict__ b1,
                            const float* __restrict__ b2,
                            const float* __restrict__ b3) {
    const int t = threadIdx.x;
    const int blk = blockIdx.x;
    if (blk < 32) {                          // W3H4: 8192 uint4 slots
        const int idx = blk * 256 + t;
        const int k16 = idx >> 9;
        const int np = (idx >> 5) & 15;
        const int lane = idx & 31;
        const int j = lane & 3, nsub = lane >> 2;
        const int n0 = np * 16 + nsub, n1 = n0 + 8;
        const int kb = k16 * 16;
        const half2 x = __floats2half2_rn(W3[n0 * 256 + kb + 2 * j],
                                          W3[n0 * 256 + kb + 2 * j + 1]);
        const half2 y = __floats2half2_rn(W3[n0 * 256 + kb + 8 + 2 * j],
                                          W3[n0 * 256 + kb + 8 + 2 * j + 1]);
        const half2 z = __floats2half2_rn(W3[n1 * 256 + kb + 2 * j],
                                          W3[n1 * 256 + kb + 2 * j + 1]);
        const half2 w = __floats2half2_rn(W3[n1 * 256 + kb + 8 + 2 * j],
                                          W3[n1 * 256 + kb + 8 + 2 * j + 1]);
        uint4 u;
        u.x = *(const uint32_t*)&x;
        u.y = *(const uint32_t*)&y;
        u.z = *(const uint32_t*)&z;
        u.w = *(const uint32_t*)&w;
        g_W3H4[idx] = u;
    } else if (blk < 36) {                   // W2H4: 1024 uint4 slots
        const int idx = (blk - 32) * 256 + t;
        const int k16 = idx >> 9;
        const int np = (idx >> 5) & 15;
        const int lane = idx & 31;
        const int j = lane & 3, nsub = lane >> 2;
        const int n0 = np * 16 + nsub, n1 = n0 + 8;
        const int kb = k16 * 16;
        const half2 x = __floats2half2_rn(W2[n0 * 32 + kb + 2 * j],
                                          W2[n0 * 32 + kb + 2 * j + 1]);
        const half2 y = __floats2half2_rn(W2[n0 * 32 + kb + 8 + 2 * j],
                                          W2[n0 * 32 + kb + 8 + 2 * j + 1]);
        const half2 z = __floats2half2_rn(W2[n1 * 32 + kb + 2 * j],
                                          W2[n1 * 32 + kb + 2 * j + 1]);
        const half2 w = __floats2half2_rn(W2[n1 * 32 + kb + 8 + 2 * j],
                                          W2[n1 * 32 + kb + 8 + 2 * j + 1]);
        uint4 u;
        u.x = *(const uint32_t*)&x;
        u.y = *(const uint32_t*)&y;
        u.z = *(const uint32_t*)&z;
        u.w = *(const uint32_t*)&w;
        g_W2H4[idx] = u;
    } else {
        __shared__ float h1[32];
        __shared__ float h2[256];
        if (t < 32) h1[t] = fmaxf(b1[t], 0.0f);
        __syncthreads();
        float a = b2[t];
#pragma unroll 8
        for (int c = 0; c < 32; c++) a += W2[t * 32 + c] * h1[c];
        h2[t] = fmaxf(a, 0.0f);
        __syncthreads();
        float o = b3[t];
#pragma unroll 8
        for (int c = 0; c < 256; c++) o += W3[t * 256 + c] * h2[c];
        g_zfeat[t] = o;
    }
}

__device__ __forceinline__ void mma_f16(float* d,
                                        uint32_t a0, uint32_t a1,
                                        uint32_t a2, uint32_t a3,
                                        uint32_t b0, uint32_t b1) {
    asm volatile(
        "mma.sync.aligned.m16n8k16.row.col.f32.f16.f16.f32 "
        "{%0,%1,%2,%3},{%4,%5,%6,%7},{%8,%9},{%0,%1,%2,%3};"
        : "+f"(d[0]), "+f"(d[1]), "+f"(d[2]), "+f"(d[3])
        : "r"(a0), "r"(a1), "r"(a2), "r"(a3), "r"(b0), "r"(b1));
}

// ---------------------------------------------------------------------------
// Main: ONE voxel per CTA, 256 threads (8 warps), warp tile M=32 x N=32,
// fp16 m16n8k16 (f32 accum). 4 CTAs/SM (35.7 KB smem, <=64 regs -> 32 warps).
// A storage K-permuted (half2 pos 2j <-> pair j, 2j+1 <-> pair j+4): each
// fragment half is one LDS.64. B: uint4 fragment-pair LDG.128 (2 per k16),
// double register-buffered, barrier-free mainloop. C kept fp32 in smem.
// ---------------------------------------------------------------------------
__global__ void __launch_bounds__(NTHREADS, 4)
voxel_tc_kernel(const float* __restrict__ fv,     // [V][32][3]
                const int*   __restrict__ fvnum,  // [V]
                const float* __restrict__ W1,     // [32][3]
                const float* __restrict__ b1,     // [32]
                const float* __restrict__ b2,     // [256]
                const float* __restrict__ b3,     // [256]
                float* __restrict__ out)          // [V][256]
{
    __shared__ float sm[480 + 32 * CS];     // 8928 floats = 35,712 B
    float* pts  = sm;                       // 96
    float* w1s  = sm + 96;                  // 96
    float* b1s  = sm + 192;                 // 32
    float* b2s  = sm + 224;                 // 256
    float* cbuf = sm + 480;                 // 32*CS f32 (C); h1/h2 half overlay
    half2* h2v  = (half2*)cbuf;             // rows: RS2 half2 stride
    half*  h1h  = (half*)cbuf;

    const int t = threadIdx.x;
    const int lane = t & 31;
    const int ng = t >> 5;                  // warp = N group (0..7), 32 cols
    const int v = blockIdx.x;
    const int num = fvnum[v];

    if (num == 0) {                         // empty voxel: constant output
        out[(size_t)v * 256 + t] = g_zfeat[t];
        return;
    }

    const int j = lane & 3;
    const int arow = lane >> 2;
    const bool m1 = num > 16;
    // uint4 slot base: np = ng*2 -> slot = np*32 + lane; k16 stride = 512
    const uint4* w2p = g_W2H4 + (ng * 2) * 32 + lane;
    const uint4* w3p = g_W3H4 + (ng * 2) * 32 + lane;

    // ---- prefetch layer-2 B (both k16 groups) while staging runs ----
    uint4 cA[2], cB[2];
    cA[0] = w2p[0];   cA[1] = w2p[32];
    cB[0] = w2p[512]; cB[1] = w2p[512 + 32];

    // ---- stage points + small params ----
    if (t < 96) pts[t] = fv[(size_t)v * 96 + t];
    else if (t < 192) w1s[t - 96] = W1[t - 96];
    else if (t < 224) b1s[t - 192] = b1[t - 192];
    b2s[t] = b2[t];
    __syncthreads();

    // ---- layer 1: 32 pts x 32 ch -> h1 (fp16, K-pair-permuted storage) ----
#pragma unroll
    for (int i = 0; i < 4; i++) {
        const int idx = t + i * 256;
        const int p = idx >> 5, k = idx & 31;
        const float a = b1s[k]
                      + w1s[k * 3 + 0] * pts[p * 3 + 0]
                      + w1s[k * 3 + 1] * pts[p * 3 + 1]
                      + w1s[k * 3 + 2] * pts[p * 3 + 2];
        const int q = k >> 1, g16 = q >> 3, jj = q & 7;
        const int pos = g16 * 8 + ((jj < 4) ? 2 * jj : 2 * (jj - 4) + 1);
        h1h[p * (RS2 * 2) + pos * 2 + (k & 1)] = __float2half_rn(fmaxf(a, 0.f));
    }
    __syncthreads();

    float acc[2][4][4];                     // [Mtile][n8][frag]
#pragma unroll
    for (int s = 0; s < 2; s++)
#pragma unroll
        for (int n = 0; n < 4; n++)
#pragma unroll
            for (int q = 0; q < 4; q++) acc[s][n][q] = 0.0f;

    // ---- layer 2: [32x32] @ W2H4, 2 k16 steps ----
#pragma unroll
    for (int k16 = 0; k16 < 2; k16++) {
        const int ap = k16 * 8 + 2 * j;     // half2 storage pos of (pair j, j+4)
        const uint2 U0 = *(const uint2*)&h2v[arow * RS2 + ap];
        const uint2 U1 = *(const uint2*)&h2v[(arow + 8) * RS2 + ap];
        uint2 U2, U3;
        if (m1) {
            U2 = *(const uint2*)&h2v[(arow + 16) * RS2 + ap];
            U3 = *(const uint2*)&h2v[(arow + 24) * RS2 + ap];
        }
#pragma unroll
        for (int n = 0; n < 4; n++) {
            const uint4 c = k16 ? cB[n >> 1] : cA[n >> 1];
            const uint32_t B0 = (n & 1) ? c.z : c.x;
            const uint32_t B1 = (n & 1) ? c.w : c.y;
            mma_f16(acc[0][n], U0.x, U1.x, U0.y, U1.y, B0, B1);
            if (m1) mma_f16(acc[1][n], U2.x, U3.x, U2.y, U3.y, B0, B1);
        }
    }

    // ---- prefetch layer-3 B (k16 = 0,1) before the store barrier ----
    cA[0] = w3p[0];   cA[1] = w3p[32];
    cB[0] = w3p[512]; cB[1] = w3p[512 + 32];
    __syncthreads();                        // all h1 reads done (overlay)

    // ---- h2 store: bias + relu -> half2, K-pair-permuted positions ----
#pragma unroll
    for (int s = 0; s < 2; s++) {
        if (s == 0 || m1) {
#pragma unroll
            for (int n = 0; n < 4; n++) {
                const int n8g = ng * 4 + n;
                const int col = n8g * 8 + 2 * j;          // channel index
                const int pos = (n8g >> 1) * 8 + 2 * j + (n8g & 1);
                const float bb0 = b2s[col], bb1 = b2s[col + 1];
                h2v[(s * 16 + arow) * RS2 + pos] = __floats2half2_rn(
                    fmaxf(acc[s][n][0] + bb0, 0.f),
                    fmaxf(acc[s][n][1] + bb1, 0.f));
                h2v[(s * 16 + arow + 8) * RS2 + pos] = __floats2half2_rn(
                    fmaxf(acc[s][n][2] + bb0, 0.f),
                    fmaxf(acc[s][n][3] + bb1, 0.f));
            }
        }
#pragma unroll
        for (int n = 0; n < 4; n++)
#pragma unroll
            for (int q = 0; q < 4; q++) acc[s][n][q] = 0.0f;
    }
    __syncthreads();                        // h2 ready for all warps

    // ---- layer 3: C[32][256] = h2 @ W3H4, 16 k16 steps, barrier-free ----
    for (int k16 = 0; k16 < 16; k16 += 2) {
#pragma unroll
        for (int half_ = 0; half_ < 2; half_++) {
            const int kk = k16 + half_;
            const int ap = kk * 8 + 2 * j;
            const uint2 U0 = *(const uint2*)&h2v[arow * RS2 + ap];
            const uint2 U1 = *(const uint2*)&h2v[(arow + 8) * RS2 + ap];
            uint2 U2, U3;
            if (m1) {
                U2 = *(const uint2*)&h2v[(arow + 16) * RS2 + ap];
                U3 = *(const uint2*)&h2v[(arow + 24) * RS2 + ap];
            }
#pragma unroll
            for (int n = 0; n < 4; n++) {
                const uint4 c = half_ ? cB[n >> 1] : cA[n >> 1];
                const uint32_t B0 = (n & 1) ? c.z : c.x;
                const uint32_t B1 = (n & 1) ? c.w : c.y;
                mma_f16(acc[0][n], U0.x, U1.x, U0.y, U1.y, B0, B1);
                if (m1) mma_f16(acc[1][n], U2.x, U3.x, U2.y, U3.y, B0, B1);
            }
            // refill consumed buffer with kk+2 (padded array: safe)
            if (half_) {
                cB[0] = w3p[(kk + 2) * 512];
                cB[1] = w3p[(kk + 2) * 512 + 32];
            } else {
                cA[0] = w3p[(kk + 2) * 512];
                cA[1] = w3p[(kk + 2) * 512 + 32];
            }
        }
    }
    __syncthreads();                        // all h2 reads done (C overlay)

    // ---- store C (fp32) into cbuf ----
#pragma unroll
    for (int s = 0; s < 2; s++) {
        if (s == 0 || m1) {
#pragma unroll
            for (int n = 0; n < 4; n++) {
                const int col = ng * 32 + n * 8 + 2 * j;
                *(float2*)&cbuf[(s * 16 + arow) * CS + col] =
                    make_float2(acc[s][n][0], acc[s][n][1]);
                *(float2*)&cbuf[(s * 16 + arow + 8) * CS + col] =
                    make_float2(acc[s][n][2], acc[s][n][3]);
            }
        }
    }
    __syncthreads();

    // ---- epilogue: masked max over valid rows + b3 ----
    float m = -CUDART_INF_F;
    for (int p = 0; p < num; p++) m = fmaxf(m, cbuf[p * CS + t]);
    out[(size_t)v * 256 + t] = m + __ldg(&b3[t]);
}

// ---------------------------------------------------------------------------
// Launch. Inputs: Frustum_Voxel, Frustum_Voxel_num, W1,b1,W2,b2,W3,b3.
// Launch period 2 -> ncu -s 5 -c 1 lands on the main kernel.
// ---------------------------------------------------------------------------
extern "C" void kernel_launch(void* const* d_in, const int* in_sizes, int n_in,
                              void* d_out, int out_size) {
    const float* fv    = (const float*)d_in[0];
    const int*   fvnum = (const int*)  d_in[1];
    const float* W1    = (const float*)d_in[2];
    const float* b1    = (const float*)d_in[3];
    const float* W2    = (const float*)d_in[4];
    const float* b2    = (const float*)d_in[5];
    const float* W3    = (const float*)d_in[6];
    const float* b3    = (const float*)d_in[7];
    float* out = (float*)d_out;

    const int V = in_sizes[1];                  // 18432 voxels

    prep_kernel<<<37, 256>>>(W2, W3, b1, b2, b3);
    voxel_tc_kernel<<<V, NTHREADS>>>(fv, fvnum, W1, b1, b2, b3, out);
}

// round 17
// speedup vs baseline: 1.1326x; 1.1326x over previous
#include <cuda_runtime.h>
#include <cuda_fp16.h>
#include <math_constants.h>
#include <cstdint>

// Problem constants (fixed by dataset: B=2, H=96, W=96, P=32)
#define NTHREADS 128
#define RS2 136   // h1/h2 row stride in half2 units: 544 B -> conflict-free
                  // LDS.64 fragment phases (per-half-warp distinct banks)
#define CS  264   // C row stride (floats): 1056 B == 32 (mod 128)

// Scratch (allocation-free rule: __device__ globals).
// uint4 fragment-major fp16 weights for mma.m16n8k16.f16:
//   slot (k16, np, lane): j=lane&3, nsub=lane>>2,
//     n0 = np*16 + nsub, n1 = n0 + 8   (covers n8 groups 2np, 2np+1)
//   .x = half2(W[n0][kb+2j],   W[n0][kb+2j+1])    (b0 of n8g=2np)
//   .y = half2(W[n0][kb+8+2j], W[n0][kb+8+2j+1])  (b1 of n8g=2np)
//   .z/.w = same with n1                           (n8g=2np+1)
// W3H4 padded by 2 k16 groups (zero) so the distance-2 prefetch may over-read.
__device__ float g_zfeat[256];
__device__ __align__(16) uint4 g_W2H4[2 * 512];
__device__ __align__(16) uint4 g_W3H4[(16 + 2) * 512];

// ---------------------------------------------------------------------------
// Prep (grid 37 x 256): blocks 0-31 W3H4, 32-35 W2H4, 36 zfeat (full fp32).
// ---------------------------------------------------------------------------
__global__ void prep_kernel(const float* __restrict__ W2,
                            const float* __restrict__ W3,
                            const float* __restrict__ b1,
                            const float* __restrict__ b2,
                            const float* __restrict__ b3) {
    const int t = threadIdx.x;
    const int blk = blockIdx.x;
    if (blk < 32) {                          // W3H4: 8192 uint4 slots
        const int idx = blk * 256 + t;
        const int k16 = idx >> 9;
        const int np = (idx >> 5) & 15;
        const int lane = idx & 31;
        const int j = lane & 3, nsub = lane >> 2;
        const int n0 = np * 16 + nsub, n1 = n0 + 8;
        const int kb = k16 * 16;
        const half2 x = __floats2half2_rn(W3[n0 * 256 + kb + 2 * j],
                                          W3[n0 * 256 + kb + 2 * j + 1]);
        const half2 y = __floats2half2_rn(W3[n0 * 256 + kb + 8 + 2 * j],
                                          W3[n0 * 256 + kb + 8 + 2 * j + 1]);
        const half2 z = __floats2half2_rn(W3[n1 * 256 + kb + 2 * j],
                                          W3[n1 * 256 + kb + 2 * j + 1]);
        const half2 w = __floats2half2_rn(W3[n1 * 256 + kb + 8 + 2 * j],
                                          W3[n1 * 256 + kb + 8 + 2 * j + 1]);
        uint4 u;
        u.x = *(const uint32_t*)&x;
        u.y = *(const uint32_t*)&y;
        u.z = *(const uint32_t*)&z;
        u.w = *(const uint32_t*)&w;
        g_W3H4[idx] = u;
    } else if (blk < 36) {                   // W2H4: 1024 uint4 slots
        const int idx = (blk - 32) * 256 + t;
        const int k16 = idx >> 9;
        const int np = (idx >> 5) & 15;
        const int lane = idx & 31;
        const int j = lane & 3, nsub = lane >> 2;
        const int n0 = np * 16 + nsub, n1 = n0 + 8;
        const int kb = k16 * 16;
        const half2 x = __floats2half2_rn(W2[n0 * 32 + kb + 2 * j],
                                          W2[n0 * 32 + kb + 2 * j + 1]);
        const half2 y = __floats2half2_rn(W2[n0 * 32 + kb + 8 + 2 * j],
                                          W2[n0 * 32 + kb + 8 + 2 * j + 1]);
        const half2 z = __floats2half2_rn(W2[n1 * 32 + kb + 2 * j],
                                          W2[n1 * 32 + kb + 2 * j + 1]);
        const half2 w = __floats2half2_rn(W2[n1 * 32 + kb + 8 + 2 * j],
                                          W2[n1 * 32 + kb + 8 + 2 * j + 1]);
        uint4 u;
        u.x = *(const uint32_t*)&x;
        u.y = *(const uint32_t*)&y;
        u.z = *(const uint32_t*)&z;
        u.w = *(const uint32_t*)&w;
        g_W2H4[idx] = u;
    } else {
        __shared__ float h1[32];
        __shared__ float h2[256];
        if (t < 32) h1[t] = fmaxf(b1[t], 0.0f);
        __syncthreads();
        float a = b2[t];
#pragma unroll 8
        for (int c = 0; c < 32; c++) a += W2[t * 32 + c] * h1[c];
        h2[t] = fmaxf(a, 0.0f);
        __syncthreads();
        float o = b3[t];
#pragma unroll 8
        for (int c = 0; c < 256; c++) o += W3[t * 256 + c] * h2[c];
        g_zfeat[t] = o;
    }
}

__device__ __forceinline__ void mma_f16(float* d,
                                        uint32_t a0, uint32_t a1,
                                        uint32_t a2, uint32_t a3,
                                        uint32_t b0, uint32_t b1) {
    asm volatile(
        "mma.sync.aligned.m16n8k16.row.col.f32.f16.f16.f32 "
        "{%0,%1,%2,%3},{%4,%5,%6,%7},{%8,%9},{%0,%1,%2,%3};"
        : "+f"(d[0]), "+f"(d[1]), "+f"(d[2]), "+f"(d[3])
        : "r"(a0), "r"(a1), "r"(a2), "r"(a3), "r"(b0), "r"(b1));
}

// ---------------------------------------------------------------------------
// Main: ONE voxel per CTA, 128 threads (4 warps), warp tile M=32 x N=64,
// fp16 m16n8k16 (f32 accum). 4 CTAs/SM (35.7 KB smem, <=128 regs -> 16 warps).
// M32/N64 minimizes L1 bytes/voxel (prop. to 1/M + 1/N): 12 KB per k16 vs
// 16 KB for M32/N32 (-25%) -- the measured L1-throughput wall (89.7%).
// A storage K-permuted (half2 pos 2j <-> pair j, 2j+1 <-> pair j+4): each
// fragment half is one LDS.64. B: uint4 fragment-pair LDG.128 (4 per k16),
// double register-buffered, barrier-free mainloop. C kept fp32 in smem.
// ---------------------------------------------------------------------------
__global__ void __launch_bounds__(NTHREADS, 4)
voxel_tc_kernel(const float* __restrict__ fv,     // [V][32][3]
                const int*   __restrict__ fvnum,  // [V]
                const float* __restrict__ W1,     // [32][3]
                const float* __restrict__ b1,     // [32]
                const float* __restrict__ b2,     // [256]
                const float* __restrict__ b3,     // [256]
                float* __restrict__ out)          // [V][256]
{
    __shared__ float sm[480 + 32 * CS];     // 8928 floats = 35,712 B
    float* pts  = sm;                       // 96
    float* w1s  = sm + 96;                  // 96
    float* b1s  = sm + 192;                 // 32
    float* b2s  = sm + 224;                 // 256
    float* cbuf = sm + 480;                 // 32*CS f32 (C); h1/h2 half overlay
    half2* h2v  = (half2*)cbuf;             // rows: RS2 half2 stride
    half*  h1h  = (half*)cbuf;

    const int t = threadIdx.x;
    const int lane = t & 31;
    const int ng = t >> 5;                  // warp = N group (0..3), 64 cols
    const int v = blockIdx.x;
    const int num = fvnum[v];

    if (num == 0) {                         // empty voxel: constant output
        out[(size_t)v * 256 + t] = g_zfeat[t];
        out[(size_t)v * 256 + t + 128] = g_zfeat[t + 128];
        return;
    }

    const int j = lane & 3;
    const int arow = lane >> 2;
    const bool m1 = num > 16;
    // uint4 slot base: np = ng*4 .. ng*4+3 -> slots (np*32 + lane)
    const uint4* w2p = g_W2H4 + (ng * 4) * 32 + lane;
    const uint4* w3p = g_W3H4 + (ng * 4) * 32 + lane;

    // ---- prefetch layer-2 B (both k16 groups) while staging runs ----
    uint4 cA[4], cB[4];
#pragma unroll
    for (int n = 0; n < 4; n++) {
        cA[n] = w2p[n * 32];
        cB[n] = w2p[512 + n * 32];
    }

    // ---- stage points + small params (128 threads) ----
    if (t < 96) { pts[t] = fv[(size_t)v * 96 + t]; w1s[t] = W1[t]; }
    if (t < 32) b1s[t] = b1[t];
    b2s[t] = b2[t];
    b2s[t + 128] = b2[t + 128];
    __syncthreads();

    // ---- layer 1: 32 pts x 32 ch -> h1 (fp16, K-pair-permuted storage) ----
#pragma unroll
    for (int i = 0; i < 8; i++) {
        const int idx = t + i * 128;
        const int p = idx >> 5, k = idx & 31;
        const float a = b1s[k]
                      + w1s[k * 3 + 0] * pts[p * 3 + 0]
                      + w1s[k * 3 + 1] * pts[p * 3 + 1]
                      + w1s[k * 3 + 2] * pts[p * 3 + 2];
        const int q = k >> 1, g16 = q >> 3, jj = q & 7;
        const int pos = g16 * 8 + ((jj < 4) ? 2 * jj : 2 * (jj - 4) + 1);
        h1h[p * (RS2 * 2) + pos * 2 + (k & 1)] = __float2half_rn(fmaxf(a, 0.f));
    }
    __syncthreads();

    float acc[2][8][4];                     // [Mtile][n8][frag]
#pragma unroll
    for (int s = 0; s < 2; s++)
#pragma unroll
        for (int n = 0; n < 8; n++)
#pragma unroll
            for (int q = 0; q < 4; q++) acc[s][n][q] = 0.0f;

    // ---- layer 2: [32x32] @ W2H4, 2 k16 steps ----
#pragma unroll
    for (int k16 = 0; k16 < 2; k16++) {
        const int ap = k16 * 8 + 2 * j;     // half2 storage pos of (pair j, j+4)
        const uint2 U0 = *(const uint2*)&h2v[arow * RS2 + ap];
        const uint2 U1 = *(const uint2*)&h2v[(arow + 8) * RS2 + ap];
        uint2 U2, U3;
        if (m1) {
            U2 = *(const uint2*)&h2v[(arow + 16) * RS2 + ap];
            U3 = *(const uint2*)&h2v[(arow + 24) * RS2 + ap];
        }
#pragma unroll
        for (int n = 0; n < 8; n++) {
            const uint4 c = k16 ? cB[n >> 1] : cA[n >> 1];
            const uint32_t B0 = (n & 1) ? c.z : c.x;
            const uint32_t B1 = (n & 1) ? c.w : c.y;
            mma_f16(acc[0][n], U0.x, U1.x, U0.y, U1.y, B0, B1);
            if (m1) mma_f16(acc[1][n], U2.x, U3.x, U2.y, U3.y, B0, B1);
        }
    }

    // ---- prefetch layer-3 B (k16 = 0,1) before the store barrier ----
#pragma unroll
    for (int n = 0; n < 4; n++) {
        cA[n] = w3p[n * 32];
        cB[n] = w3p[512 + n * 32];
    }
    __syncthreads();                        // all h1 reads done (overlay)

    // ---- h2 store: bias + relu -> half2, K-pair-permuted positions ----
#pragma unroll
    for (int s = 0; s < 2; s++) {
        if (s == 0 || m1) {
#pragma unroll
            for (int n = 0; n < 8; n++) {
                const int n8g = ng * 8 + n;
                const int col = n8g * 8 + 2 * j;          // channel index
                const int pos = (n8g >> 1) * 8 + 2 * j + (n8g & 1);
                const float bb0 = b2s[col], bb1 = b2s[col + 1];
                h2v[(s * 16 + arow) * RS2 + pos] = __floats2half2_rn(
                    fmaxf(acc[s][n][0] + bb0, 0.f),
                    fmaxf(acc[s][n][1] + bb1, 0.f));
                h2v[(s * 16 + arow + 8) * RS2 + pos] = __floats2half2_rn(
                    fmaxf(acc[s][n][2] + bb0, 0.f),
                    fmaxf(acc[s][n][3] + bb1, 0.f));
            }
        }
#pragma unroll
        for (int n = 0; n < 8; n++)
#pragma unroll
            for (int q = 0; q < 4; q++) acc[s][n][q] = 0.0f;
    }
    __syncthreads();                        // h2 ready for all warps

    // ---- layer 3: C[32][256] = h2 @ W3H4, 16 k16 steps, barrier-free ----
    for (int k16 = 0; k16 < 16; k16 += 2) {
#pragma unroll
        for (int half_ = 0; half_ < 2; half_++) {
            const int kk = k16 + half_;
            const int ap = kk * 8 + 2 * j;
            const uint2 U0 = *(const uint2*)&h2v[arow * RS2 + ap];
            const uint2 U1 = *(const uint2*)&h2v[(arow + 8) * RS2 + ap];
            uint2 U2, U3;
            if (m1) {
                U2 = *(const uint2*)&h2v[(arow + 16) * RS2 + ap];
                U3 = *(const uint2*)&h2v[(arow + 24) * RS2 + ap];
            }
#pragma unroll
            for (int n = 0; n < 8; n++) {
                const uint4 c = half_ ? cB[n >> 1] : cA[n >> 1];
                const uint32_t B0 = (n & 1) ? c.z : c.x;
                const uint32_t B1 = (n & 1) ? c.w : c.y;
                mma_f16(acc[0][n], U0.x, U1.x, U0.y, U1.y, B0, B1);
                if (m1) mma_f16(acc[1][n], U2.x, U3.x, U2.y, U3.y, B0, B1);
            }
            // refill consumed buffer with kk+2 (padded array: safe)
#pragma unroll
            for (int n = 0; n < 4; n++) {
                if (half_) cB[n] = w3p[(kk + 2) * 512 + n * 32];
                else       cA[n] = w3p[(kk + 2) * 512 + n * 32];
            }
        }
    }
    __syncthreads();                        // all h2 reads done (C overlay)

    // ---- store C (fp32) into cbuf ----
#pragma unroll
    for (int s = 0; s < 2; s++) {
        if (s == 0 || m1) {
#pragma unroll
            for (int n = 0; n < 8; n++) {
                const int col = ng * 64 + n * 8 + 2 * j;
                *(float2*)&cbuf[(s * 16 + arow) * CS + col] =
                    make_float2(acc[s][n][0], acc[s][n][1]);
                *(float2*)&cbuf[(s * 16 + arow + 8) * CS + col] =
                    make_float2(acc[s][n][2], acc[s][n][3]);
            }
        }
    }
    __syncthreads();

    // ---- epilogue: masked max over valid rows + b3 (2 channels/thread) ----
    float m0 = -CUDART_INF_F, m1v = -CUDART_INF_F;
    for (int p = 0; p < num; p++) {
        m0  = fmaxf(m0,  cbuf[p * CS + t]);
        m1v = fmaxf(m1v, cbuf[p * CS + t + 128]);
    }
    out[(size_t)v * 256 + t] = m0 + __ldg(&b3[t]);
    out[(size_t)v * 256 + t + 128] = m1v + __ldg(&b3[t + 128]);
}

// ---------------------------------------------------------------------------
// Launch. Inputs: Frustum_Voxel, Frustum_Voxel_num, W1,b1,W2,b2,W3,b3.
// Launch period 2 -> ncu -s 5 -c 1 lands on the main kernel.
// ---------------------------------------------------------------------------
extern "C" void kernel_launch(void* const* d_in, const int* in_sizes, int n_in,
                              void* d_out, int out_size) {
    const float* fv    = (const float*)d_in[0];
    const int*   fvnum = (const int*)  d_in[1];
    const float* W1    = (const float*)d_in[2];
    const float* b1    = (const float*)d_in[3];
    const float* W2    = (const float*)d_in[4];
    const float* b2    = (const float*)d_in[5];
    const float* W3    = (const float*)d_in[6];
    const float* b3    = (const float*)d_in[7];
    float* out = (float*)d_out;

    const int V = in_sizes[1];                  // 18432 voxels

    prep_kernel<<<37, 256>>>(W2, W3, b1, b2, b3);
    voxel_tc_kernel<<<V, NTHREADS>>>(fv, fvnum, W1, b1, b2, b3, out);
}